// round 12
// baseline (speedup 1.0000x reference)
#include <cuda_runtime.h>
#include <cuda_fp16.h>
#include <cstdint>

#define BB 8
#define CC 256
#define HH 64
#define WW 64
#define OO 256
#define KK2 9
#define PLANE 4096
#define KEFF 2304          // 16 cgroups * 9 taps * 16 ch
#define KSTAGE 64
#define NSTAGES (KEFF / KSTAGE)   // 36
#define NPIPE 3
#define PITCH 144                 // smem row pitch bytes (128B data + 16 pad)
#define AST (128 * PITCH)         // 18432 per A stage
#define BST (128 * PITCH)         // 18432 per B stage
#define SM_B0 (NPIPE * AST)       // 55296
#define SMEM_TOTAL (SM_B0 + NPIPE * BST)   // 110592

// ---------------- device scratch ----------------
__device__ __half g_wa[OO * KEFF];                        // A: [o][keff]
__device__ __half g_xh[(size_t)BB * 16 * PLANE * 16];     // NHWC 16-ch groups
__device__ __half g_im[(size_t)BB * PLANE * KEFF];        // im2col B: [b][px][keff]

// ---------------- helpers ----------------
__device__ __forceinline__ uint32_t smem_u32(const void* p) {
    uint32_t a;
    asm("{ .reg .u64 t; cvta.to.shared.u64 t, %1; cvt.u32.u64 %0, t; }"
        : "=r"(a) : "l"(p));
    return a;
}
__device__ __forceinline__ void cpa16(uint32_t dst, const void* src) {
    asm volatile("cp.async.cg.shared.global [%0], [%1], 16;"
                 :: "r"(dst), "l"(src));
}
__device__ __forceinline__ void cpa_commit() {
    asm volatile("cp.async.commit_group;");
}
__device__ __forceinline__ void cpa_wait1() {
    asm volatile("cp.async.wait_group 1;");
}
__device__ __forceinline__ void ldmx4(uint32_t* r, uint32_t addr) {
    asm volatile("ldmatrix.sync.aligned.m8n8.x4.shared.b16 {%0,%1,%2,%3}, [%4];"
                 : "=r"(r[0]), "=r"(r[1]), "=r"(r[2]), "=r"(r[3]) : "r"(addr));
}
__device__ __forceinline__ void mma16816(float* d, const uint32_t* a,
                                         uint32_t b0, uint32_t b1) {
    asm volatile(
        "mma.sync.aligned.m16n8k16.row.col.f32.f16.f16.f32 "
        "{%0,%1,%2,%3}, {%4,%5,%6,%7}, {%8,%9}, {%0,%1,%2,%3};"
        : "+f"(d[0]), "+f"(d[1]), "+f"(d[2]), "+f"(d[3])
        : "r"(a[0]), "r"(a[1]), "r"(a[2]), "r"(a[3]), "r"(b0), "r"(b1));
}

// ---------------- prep kernels ----------------
__global__ void prep_wa(const float* __restrict__ w) {
    int n = blockIdx.x * blockDim.x + threadIdx.x;   // over 256*2304
    if (n >= OO * KEFF) return;
    int keff = n % KEFF;
    int o    = n / KEFF;
    int q  = keff >> 4;
    int cl = keff & 15;
    int cg = q / KK2;
    int k  = q - cg * KK2;
    int c  = cg * 16 + cl;
    g_wa[n] = __float2half(w[(o * CC + c) * KK2 + k]);
}

__global__ void prep_x(const float* __restrict__ x) {
    int n = blockIdx.x * blockDim.x + threadIdx.x;   // over 8*16*4096
    if (n >= BB * 16 * PLANE) return;
    int pix = n & 4095;
    int cg  = (n >> 12) & 15;
    int b   = n >> 16;
    const float* src = x + ((size_t)b * CC + cg * 16) * PLANE + pix;
    __half hbuf[16];
#pragma unroll
    for (int j = 0; j < 16; j++)
        hbuf[j] = __float2half(src[(size_t)j * PLANE]);
    uint4* dst = (uint4*)(g_xh + ((size_t)(b * 16 + cg) * PLANE + pix) * 16);
    dst[0] = *(uint4*)&hbuf[0];
    dst[1] = *(uint4*)&hbuf[8];
}

// ---------------- im2col: one tap per thread, 16 cgroups reuse it ----------------
__global__ __launch_bounds__(256) void im2col(const float* __restrict__ offset) {
    const int tid = threadIdx.x;
    const int g   = tid & 1;          // 8-channel group
    const int pxl = tid >> 1;         // 0..127
    const int px  = blockIdx.x * 128 + pxl;
    const int k   = blockIdx.y;       // tap 0..8
    const int b   = blockIdx.z;

    const int h  = px >> 6, wc = px & 63;
    const int ky = k / 3,  kx = k - ky * 3;
    float dy = offset[((b * 2 * KK2 + 2 * k    ) * PLANE) + px];
    float dx = offset[((b * 2 * KK2 + 2 * k + 1) * PLANE) + px];
    float py  = (float)(h - 1 + ky) + dy;
    float pxf = (float)(wc - 1 + kx) + dx;
    float y0f = floorf(py), x0f = floorf(pxf);
    float fy = py - y0f, fx = pxf - x0f;
    int y0 = (int)y0f, x0 = (int)x0f;
    int y1 = y0 + 1,  x1 = x0 + 1;
    bool vy0 = (y0 >= 0) && (y0 < HH);
    bool vy1 = (y1 >= 0) && (y1 < HH);
    bool vx0 = (x0 >= 0) && (x0 < WW);
    bool vx1 = (x1 >= 0) && (x1 < WW);
    float cw0 = (vy0 && vx0) ? (1.f - fy) * (1.f - fx) : 0.f;
    float cw1 = (vy0 && vx1) ? (1.f - fy) * fx : 0.f;
    float cw2 = (vy1 && vx0) ? fy * (1.f - fx) : 0.f;
    float cw3 = (vy1 && vx1) ? fy * fx : 0.f;
    int cy0 = min(max(y0, 0), HH - 1), cy1 = min(max(y1, 0), HH - 1);
    int cx0 = min(max(x0, 0), WW - 1), cx1 = min(max(x1, 0), WW - 1);
    int i00 = cy0 * WW + cx0, i01 = cy0 * WW + cx1;
    int i10 = cy1 * WW + cx0, i11 = cy1 * WW + cx1;

    const char* xb = (const char*)g_xh + (size_t)b * 16 * PLANE * 32 + g * 16;
    __half* dst = g_im + ((size_t)(b * PLANE + px)) * KEFF + k * 16 + g * 8;

#pragma unroll 4
    for (int cg = 0; cg < 16; cg++) {
        const char* pb = xb + (size_t)cg * (PLANE * 32);
        uint4 c00 = __ldg((const uint4*)(pb + i00 * 32));
        uint4 c01 = __ldg((const uint4*)(pb + i01 * 32));
        uint4 c10 = __ldg((const uint4*)(pb + i10 * 32));
        uint4 c11 = __ldg((const uint4*)(pb + i11 * 32));
        const __half2* H00 = (const __half2*)&c00;
        const __half2* H01 = (const __half2*)&c01;
        const __half2* H10 = (const __half2*)&c10;
        const __half2* H11 = (const __half2*)&c11;
        uint32_t sbuf[4];
#pragma unroll
        for (int j = 0; j < 4; j++) {
            float2 f00 = __half22float2(H00[j]);
            float2 f01 = __half22float2(H01[j]);
            float2 f10 = __half22float2(H10[j]);
            float2 f11 = __half22float2(H11[j]);
            float s0 = cw0 * f00.x + cw1 * f01.x + cw2 * f10.x + cw3 * f11.x;
            float s1 = cw0 * f00.y + cw1 * f01.y + cw2 * f10.y + cw3 * f11.y;
            __half2 hh = __floats2half2_rn(s0, s1);
            sbuf[j] = *(uint32_t*)&hh;
        }
        *(uint4*)(dst + cg * (KK2 * 16)) = *(uint4*)&sbuf[0];
    }
}

// -------- GEMM: 128x128 CTA, 256 thr, 3-stage x 64-K cp.async pipeline --------
__global__ __launch_bounds__(256, 2)
void gemm_kernel(float* __restrict__ out) {
    extern __shared__ char smem[];
    const uint32_t sb = smem_u32(smem);
    const int tid = threadIdx.x;
    const int lid = tid & 31;
    const int wid = tid >> 5;
    const int wm  = wid >> 2;       // 0..1 : 64 o-rows each
    const int wn  = wid & 3;        // 0..3 : 32 px each
    const int b   = blockIdx.y;
    const int mh  = blockIdx.x & 1;           // o-half (paired for L2 reuse)
    const int px0 = (blockIdx.x >> 1) * 128;

    // cp.async: row = tid>>1, each thread loads 64B (4 x cpa16) of A and B
    const int row  = tid >> 1;
    const int seg0 = (tid & 1) * 64;
    const char* a_src0 = (const char*)g_wa
        + ((size_t)(mh * 128 + row)) * KEFF * 2 + seg0;
    const char* b_src0 = (const char*)g_im
        + ((size_t)(b * PLANE + px0 + row)) * KEFF * 2 + seg0;
    const uint32_t a_dst = sb + row * PITCH + seg0;
    const uint32_t b_dst = sb + SM_B0 + row * PITCH + seg0;

    // frag addressing
    const int r   = lid & 7;
    const int sec = lid >> 3;
    const uint32_t aoff = (uint32_t)(wm * 64 + r + 8 * (sec & 1)) * PITCH
                        + (uint32_t)(sec >> 1) * 16;
    const uint32_t boff = (uint32_t)(wn * 32 + r + 8 * (sec >> 1)) * PITCH
                        + (uint32_t)(sec & 1) * 16;

    float acc[4][4][4];
#pragma unroll
    for (int i = 0; i < 4; i++)
#pragma unroll
        for (int j = 0; j < 4; j++)
#pragma unroll
            for (int t = 0; t < 4; t++) acc[i][j][t] = 0.f;

    auto issue = [&](int st, int s) {
        const char* asrc = a_src0 + st * (KSTAGE * 2);
        const char* bsrc = b_src0 + st * (KSTAGE * 2);
        uint32_t ad = a_dst + s * AST;
        uint32_t bd = b_dst + s * BST;
#pragma unroll
        for (int j = 0; j < 4; j++) {
            cpa16(ad + j * 16, asrc + j * 16);
            cpa16(bd + j * 16, bsrc + j * 16);
        }
        cpa_commit();
    };

    issue(0, 0);
    issue(1, 1);

    for (int st = 0; st < NSTAGES; st++) {
        const int s = st % NPIPE;
        cpa_wait1();
        __syncthreads();
        // slot (st-1)%3 == (st+2)%3 is free for all warps now
        if (st + 2 < NSTAGES) issue(st + 2, (st + 2) % NPIPE);
        else cpa_commit();   // empty group keeps wait_group accounting exact

        const uint32_t abase = sb + s * AST;
        const uint32_t bbase = sb + SM_B0 + s * BST;
#pragma unroll
        for (int ks = 0; ks < 4; ks++) {
            uint32_t af[4][4], bf[2][4];
#pragma unroll
            for (int mt = 0; mt < 4; mt++)
                ldmx4(af[mt], abase + aoff + mt * 16 * PITCH + ks * 32);
#pragma unroll
            for (int ng = 0; ng < 2; ng++)
                ldmx4(bf[ng], bbase + boff + ng * 16 * PITCH + ks * 32);
#pragma unroll
            for (int mt = 0; mt < 4; mt++)
#pragma unroll
                for (int ng = 0; ng < 2; ng++) {
                    mma16816(acc[mt][2 * ng],     af[mt], bf[ng][0], bf[ng][1]);
                    mma16816(acc[mt][2 * ng + 1], af[mt], bf[ng][2], bf[ng][3]);
                }
        }
    }

    // epilogue: out[b][o][px]
    const int ml = lid >> 2;
    const int nl = (lid & 3) * 2;
#pragma unroll
    for (int mt = 0; mt < 4; mt++) {
#pragma unroll
        for (int nt = 0; nt < 4; nt++) {
            int o  = mh * 128 + wm * 64 + mt * 16 + ml;
            int px = px0 + wn * 32 + nt * 8 + nl;
            float* op = out + ((size_t)b * OO + o) * PLANE + px;
            *(float2*)op = make_float2(acc[mt][nt][0], acc[mt][nt][1]);
            float* op2 = op + (size_t)8 * PLANE;   // o + 8
            *(float2*)op2 = make_float2(acc[mt][nt][2], acc[mt][nt][3]);
        }
    }
}

extern "C" void kernel_launch(void* const* d_in, const int* in_sizes, int n_in,
                              void* d_out, int out_size) {
    const float* x      = (const float*)d_in[0];   // [8,256,64,64]
    const float* offset = (const float*)d_in[1];   // [8,18,64,64]
    const float* weight = (const float*)d_in[2];   // [256,256,3,3]
    float* out = (float*)d_out;                    // [8,256,64,64]

    cudaFuncSetAttribute(gemm_kernel,
                         cudaFuncAttributeMaxDynamicSharedMemorySize, SMEM_TOTAL);

    int nw = OO * KEFF;
    prep_wa<<<(nw + 255) / 256, 256>>>(weight);
    int nx = BB * 16 * PLANE;
    prep_x<<<(nx + 255) / 256, 256>>>(x);

    dim3 g_im2(PLANE / 128, KK2, BB);        // 32 x 9 x 8
    im2col<<<g_im2, 256>>>(offset);

    dim3 g_gemm(2 * (PLANE / 128), BB);      // 64 x 8 = 512 CTAs (mh paired)
    gemm_kernel<<<g_gemm, 256, SMEM_TOTAL>>>(out);
}

// round 13
// speedup vs baseline: 1.7188x; 1.7188x over previous
#include <cuda_runtime.h>
#include <cuda_fp16.h>
#include <cstdint>

#define BB 8
#define CC 256
#define HH 64
#define WW 64
#define OO 256
#define KK2 9
#define PLANE 4096
#define KEFF 2304          // 16 cgroups * 9 taps * 16 ch
#define KSTAGE 32
#define NSTAGES (KEFF / KSTAGE)   // 72
#define NPIPE 4
#define PITCH 80                  // smem row pitch bytes (64B data + 16 pad)
#define AST (128 * PITCH)         // 10240 per A stage
#define BST (128 * PITCH)         // 10240 per B stage
#define SM_B0 (NPIPE * AST)       // 40960
#define SMEM_TOTAL (SM_B0 + NPIPE * BST)   // 81920

// ---------------- device scratch ----------------
__device__ __half g_wa[OO * KEFF];                        // A: [o][keff]
__device__ __half g_xh[(size_t)BB * 16 * PLANE * 16];     // NHWC 16-ch groups
__device__ __half g_im[(size_t)BB * PLANE * KEFF];        // im2col B: [b][px][keff]

// ---------------- helpers ----------------
__device__ __forceinline__ uint32_t smem_u32(const void* p) {
    uint32_t a;
    asm("{ .reg .u64 t; cvta.to.shared.u64 t, %1; cvt.u32.u64 %0, t; }"
        : "=r"(a) : "l"(p));
    return a;
}
__device__ __forceinline__ void cpa16(uint32_t dst, const void* src) {
    asm volatile("cp.async.cg.shared.global [%0], [%1], 16;"
                 :: "r"(dst), "l"(src));
}
__device__ __forceinline__ void cpa_commit() {
    asm volatile("cp.async.commit_group;");
}
__device__ __forceinline__ void cpa_wait2() {
    asm volatile("cp.async.wait_group 2;");
}
__device__ __forceinline__ void ldmx4(uint32_t* r, uint32_t addr) {
    asm volatile("ldmatrix.sync.aligned.m8n8.x4.shared.b16 {%0,%1,%2,%3}, [%4];"
                 : "=r"(r[0]), "=r"(r[1]), "=r"(r[2]), "=r"(r[3]) : "r"(addr));
}
__device__ __forceinline__ void mma16816(float* d, const uint32_t* a,
                                         uint32_t b0, uint32_t b1) {
    asm volatile(
        "mma.sync.aligned.m16n8k16.row.col.f32.f16.f16.f32 "
        "{%0,%1,%2,%3}, {%4,%5,%6,%7}, {%8,%9}, {%0,%1,%2,%3};"
        : "+f"(d[0]), "+f"(d[1]), "+f"(d[2]), "+f"(d[3])
        : "r"(a[0]), "r"(a[1]), "r"(a[2]), "r"(a[3]), "r"(b0), "r"(b1));
}

// ---------------- prep kernels ----------------
__global__ void prep_wa(const float* __restrict__ w) {
    int n = blockIdx.x * blockDim.x + threadIdx.x;   // over 256*2304
    if (n >= OO * KEFF) return;
    int keff = n % KEFF;
    int o    = n / KEFF;
    int q  = keff >> 4;
    int cl = keff & 15;
    int cg = q / KK2;
    int k  = q - cg * KK2;
    int c  = cg * 16 + cl;
    g_wa[n] = __float2half(w[(o * CC + c) * KK2 + k]);
}

__global__ void prep_x(const float* __restrict__ x) {
    int n = blockIdx.x * blockDim.x + threadIdx.x;   // over 8*16*4096
    if (n >= BB * 16 * PLANE) return;
    int pix = n & 4095;
    int cg  = (n >> 12) & 15;
    int b   = n >> 16;
    const float* src = x + ((size_t)b * CC + cg * 16) * PLANE + pix;
    __half hbuf[16];
#pragma unroll
    for (int j = 0; j < 16; j++)
        hbuf[j] = __float2half(src[(size_t)j * PLANE]);
    uint4* dst = (uint4*)(g_xh + ((size_t)(b * 16 + cg) * PLANE + pix) * 16);
    dst[0] = *(uint4*)&hbuf[0];
    dst[1] = *(uint4*)&hbuf[8];
}

// ---------------- im2col: one tap per thread, 16 cgroups reuse it ----------------
__global__ __launch_bounds__(256) void im2col(const float* __restrict__ offset) {
    const int tid = threadIdx.x;
    const int g   = tid & 1;          // 8-channel group
    const int pxl = tid >> 1;         // 0..127
    const int px  = blockIdx.x * 128 + pxl;
    const int k   = blockIdx.y;       // tap 0..8
    const int b   = blockIdx.z;

    const int h  = px >> 6, wc = px & 63;
    const int ky = k / 3,  kx = k - ky * 3;
    float dy = offset[((b * 2 * KK2 + 2 * k    ) * PLANE) + px];
    float dx = offset[((b * 2 * KK2 + 2 * k + 1) * PLANE) + px];
    float py  = (float)(h - 1 + ky) + dy;
    float pxf = (float)(wc - 1 + kx) + dx;
    float y0f = floorf(py), x0f = floorf(pxf);
    float fy = py - y0f, fx = pxf - x0f;
    int y0 = (int)y0f, x0 = (int)x0f;
    int y1 = y0 + 1,  x1 = x0 + 1;
    bool vy0 = (y0 >= 0) && (y0 < HH);
    bool vy1 = (y1 >= 0) && (y1 < HH);
    bool vx0 = (x0 >= 0) && (x0 < WW);
    bool vx1 = (x1 >= 0) && (x1 < WW);
    float cw0 = (vy0 && vx0) ? (1.f - fy) * (1.f - fx) : 0.f;
    float cw1 = (vy0 && vx1) ? (1.f - fy) * fx : 0.f;
    float cw2 = (vy1 && vx0) ? fy * (1.f - fx) : 0.f;
    float cw3 = (vy1 && vx1) ? fy * fx : 0.f;
    int cy0 = min(max(y0, 0), HH - 1), cy1 = min(max(y1, 0), HH - 1);
    int cx0 = min(max(x0, 0), WW - 1), cx1 = min(max(x1, 0), WW - 1);
    int i00 = cy0 * WW + cx0, i01 = cy0 * WW + cx1;
    int i10 = cy1 * WW + cx0, i11 = cy1 * WW + cx1;

    const char* xb = (const char*)g_xh + (size_t)b * 16 * PLANE * 32 + g * 16;
    __half* dst = g_im + ((size_t)(b * PLANE + px)) * KEFF + k * 16 + g * 8;

#pragma unroll 4
    for (int cg = 0; cg < 16; cg++) {
        const char* pb = xb + (size_t)cg * (PLANE * 32);
        uint4 c00 = __ldg((const uint4*)(pb + i00 * 32));
        uint4 c01 = __ldg((const uint4*)(pb + i01 * 32));
        uint4 c10 = __ldg((const uint4*)(pb + i10 * 32));
        uint4 c11 = __ldg((const uint4*)(pb + i11 * 32));
        const __half2* H00 = (const __half2*)&c00;
        const __half2* H01 = (const __half2*)&c01;
        const __half2* H10 = (const __half2*)&c10;
        const __half2* H11 = (const __half2*)&c11;
        uint32_t sbuf[4];
#pragma unroll
        for (int j = 0; j < 4; j++) {
            float2 f00 = __half22float2(H00[j]);
            float2 f01 = __half22float2(H01[j]);
            float2 f10 = __half22float2(H10[j]);
            float2 f11 = __half22float2(H11[j]);
            float s0 = cw0 * f00.x + cw1 * f01.x + cw2 * f10.x + cw3 * f11.x;
            float s1 = cw0 * f00.y + cw1 * f01.y + cw2 * f10.y + cw3 * f11.y;
            __half2 hh = __floats2half2_rn(s0, s1);
            sbuf[j] = *(uint32_t*)&hh;
        }
        *(uint4*)(dst + cg * (KK2 * 16)) = *(uint4*)&sbuf[0];
    }
}

// -------- GEMM: 128x128 CTA, 256 thr, 4-stage cp.async, mh-paired grid --------
__global__ __launch_bounds__(256, 2)
void gemm_kernel(float* __restrict__ out) {
    extern __shared__ char smem[];
    const uint32_t sb = smem_u32(smem);
    const int tid = threadIdx.x;
    const int lid = tid & 31;
    const int wid = tid >> 5;
    const int wm  = wid >> 2;       // 0..1 : 64 o-rows each
    const int wn  = wid & 3;        // 0..3 : 32 px each
    const int b   = blockIdx.y;
    const int mh  = blockIdx.x & 1;           // o-half (paired for B L2 reuse)
    const int px0 = (blockIdx.x >> 1) * 128;

    // cp.async assignment: 2 A segs + 2 B segs per thread per stage
    const int row  = tid >> 1;          // 0..127
    const int seg0 = (tid & 1) * 2;     // 0 or 2
    const char* a_src0 = (const char*)g_wa
        + ((size_t)(mh * 128 + row)) * KEFF * 2 + seg0 * 16;
    const char* b_src0 = (const char*)g_im
        + ((size_t)(b * PLANE + px0 + row)) * KEFF * 2 + seg0 * 16;
    const uint32_t a_dst = sb + row * PITCH + seg0 * 16;
    const uint32_t b_dst = sb + SM_B0 + row * PITCH + seg0 * 16;

    // frag addressing
    const int r   = lid & 7;
    const int sec = lid >> 3;
    const uint32_t aoff = (uint32_t)(wm * 64 + r + 8 * (sec & 1)) * PITCH
                        + (uint32_t)(sec >> 1) * 16;
    const uint32_t boff = (uint32_t)(wn * 32 + r + 8 * (sec >> 1)) * PITCH
                        + (uint32_t)(sec & 1) * 16;

    float acc[4][4][4];
#pragma unroll
    for (int i = 0; i < 4; i++)
#pragma unroll
        for (int j = 0; j < 4; j++)
#pragma unroll
            for (int t = 0; t < 4; t++) acc[i][j][t] = 0.f;

    auto issue = [&](int st, int s) {
        const char* asrc = a_src0 + (st * KSTAGE) * 2;
        const char* bsrc = b_src0 + (st * KSTAGE) * 2;
        cpa16(a_dst + s * AST,      asrc);
        cpa16(a_dst + s * AST + 16, asrc + 16);
        cpa16(b_dst + s * BST,      bsrc);
        cpa16(b_dst + s * BST + 16, bsrc + 16);
        cpa_commit();
    };

    issue(0, 0);
    issue(1, 1);
    issue(2, 2);

    for (int st = 0; st < NSTAGES; st++) {
        const int s = st & (NPIPE - 1);
        cpa_wait2();
        __syncthreads();

        // slot (st+3)%4 == (st-1)%4 was last READ in iteration st-1, which all
        // threads completed before the barrier above -> safe to refill now.
        if (st + 3 < NSTAGES) issue(st + 3, (st + 3) & (NPIPE - 1));
        else cpa_commit();   // empty group keeps wait_group accounting exact

        const uint32_t abase = sb + s * AST;
        const uint32_t bbase = sb + SM_B0 + s * BST;
#pragma unroll
        for (int ks = 0; ks < 2; ks++) {
            uint32_t af[4][4], bf[2][4];
#pragma unroll
            for (int mt = 0; mt < 4; mt++)
                ldmx4(af[mt], abase + aoff + mt * 16 * PITCH + ks * 32);
#pragma unroll
            for (int ng = 0; ng < 2; ng++)
                ldmx4(bf[ng], bbase + boff + ng * 16 * PITCH + ks * 32);
#pragma unroll
            for (int mt = 0; mt < 4; mt++)
#pragma unroll
                for (int ng = 0; ng < 2; ng++) {
                    mma16816(acc[mt][2 * ng],     af[mt], bf[ng][0], bf[ng][1]);
                    mma16816(acc[mt][2 * ng + 1], af[mt], bf[ng][2], bf[ng][3]);
                }
        }
    }

    // epilogue: out[b][o][px]
    const int ml = lid >> 2;
    const int nl = (lid & 3) * 2;
#pragma unroll
    for (int mt = 0; mt < 4; mt++) {
#pragma unroll
        for (int nt = 0; nt < 4; nt++) {
            int o  = mh * 128 + wm * 64 + mt * 16 + ml;
            int px = px0 + wn * 32 + nt * 8 + nl;
            float* op = out + ((size_t)b * OO + o) * PLANE + px;
            *(float2*)op = make_float2(acc[mt][nt][0], acc[mt][nt][1]);
            float* op2 = op + (size_t)8 * PLANE;   // o + 8
            *(float2*)op2 = make_float2(acc[mt][nt][2], acc[mt][nt][3]);
        }
    }
}

extern "C" void kernel_launch(void* const* d_in, const int* in_sizes, int n_in,
                              void* d_out, int out_size) {
    const float* x      = (const float*)d_in[0];   // [8,256,64,64]
    const float* offset = (const float*)d_in[1];   // [8,18,64,64]
    const float* weight = (const float*)d_in[2];   // [256,256,3,3]
    float* out = (float*)d_out;                    // [8,256,64,64]

    cudaFuncSetAttribute(gemm_kernel,
                         cudaFuncAttributeMaxDynamicSharedMemorySize, SMEM_TOTAL);

    int nw = OO * KEFF;
    prep_wa<<<(nw + 255) / 256, 256>>>(weight);
    int nx = BB * 16 * PLANE;
    prep_x<<<(nx + 255) / 256, 256>>>(x);

    dim3 g_im2(PLANE / 128, KK2, BB);        // 32 x 9 x 8
    im2col<<<g_im2, 256>>>(offset);

    dim3 g_gemm(2 * (PLANE / 128), BB);      // 64 x 8 = 512 CTAs (mh paired)
    gemm_kernel<<<g_gemm, 256, SMEM_TOTAL>>>(out);
}